// round 3
// baseline (speedup 1.0000x reference)
#include <cuda_runtime.h>
#include <cstdint>

typedef unsigned long long u64;

#define DEVINL __device__ __forceinline__

DEVINL u64 pack2(float lo, float hi) {
    u64 d;
    asm("mov.b64 %0, {%1, %2};" : "=l"(d) : "f"(lo), "f"(hi));
    return d;
}
DEVINL void unpack2(u64 v, float& lo, float& hi) {
    asm("mov.b64 {%0, %1}, %2;" : "=f"(lo), "=f"(hi) : "l"(v));
}
DEVINL u64 ffma2(u64 a, u64 b, u64 c) {
    u64 d;
    asm("fma.rn.f32x2 %0, %1, %2, %3;" : "=l"(d) : "l"(a), "l"(b), "l"(c));
    return d;
}

// smooth_leaky_relu(x) = 0.6x + 0.4x*tanh(x/2)   (alpha=0.2)
DEVINL float act_fn(float v) {
    float t;
    asm("tanh.approx.f32 %0, %1;" : "=f"(t) : "f"(0.5f * v));
    return v * (0.6f + 0.4f * t);
}

static constexpr int ROWLEN = 592;

// transposed-weight scratch: Wt[k][o] per segment, packed back-to-back
__device__ float g_wt[16384 + 4096 + 1024 + 256];

__global__ void prep_kernel(const float* __restrict__ w0, const float* __restrict__ w1,
                            const float* __restrict__ w2, const float* __restrict__ w3) {
    int idx = blockIdx.x * 256 + threadIdx.x;
    if (idx < 16384) {
        int k = idx >> 7, o = idx & 127;
        g_wt[idx] = w0[o * 128 + k];
    } else if (idx < 20480) {
        int t = idx - 16384; int k = t >> 6, o = t & 63;
        g_wt[idx] = w1[o * 64 + k];
    } else if (idx < 21504) {
        int t = idx - 20480; int k = t >> 5, o = t & 31;
        g_wt[idx] = w2[o * 32 + k];
    } else if (idx < 21760) {
        int t = idx - 21504; int k = t >> 4, o = t & 15;
        g_wt[idx] = w3[o * 16 + k];
    }
}

// Layouts:
//   Xs (u64): [kchunk][column]  pitch PCp = CBLK+1,  Xs[k*PCp + c] = {x,x} pair
//             column c = r*D + dd  (r = row-in-block, dd = d index)
//   Os (f32): [column][output]  pitch PO = MUL+1,    Os[c*PO + o]
//   Ws (f32): [k][o]            (pre-transposed by prep_kernel)
//
// Warps split outputs into OW groups of TO, and K into KSPLIT groups (partials
// summed in epilogue). X is loaded in KPH phases re-using one smem buffer.
template<int MUL, int D, int R, int NW, int TO, int KSPLIT, int KPH,
         int IN_OFF, int WOFF, bool ACT, int MINB>
__global__ __launch_bounds__(NW * 32, MINB)
void seg_kernel(const float* __restrict__ x, const float* __restrict__ bias,
                float* __restrict__ out, int N) {
    constexpr int NT     = NW * 32;
    constexpr int CBLK   = R * D;
    constexpr int TC     = CBLK / 32;
    constexpr int SEGLEN = MUL * D;
    constexpr int SEGF4  = SEGLEN / 4;
    constexpr int K      = MUL;
    constexpr int KCH    = K / KPH;          // k per load phase
    constexpr int CHLEN  = SEGLEN / KPH;     // row elements per phase
    constexpr int CHF4   = CHLEN / 4;
    constexpr int KLEN   = KCH / KSPLIT;     // k per warp k-group per phase
    constexpr int OW     = MUL / TO;
    constexpr int TOH    = TO / 2;
    constexpr int PCp    = CBLK + 1;
    constexpr int PO     = MUL + 1;
    constexpr int XS2_F  = KCH * PCp * 2;
    constexpr int OS_F   = CBLK * PO;
    constexpr int REG_F  = (XS2_F > OS_F ? XS2_F : OS_F);

    extern __shared__ float smem[];
    float* Ws  = smem;
    u64*   Xs  = (u64*)(smem + K * MUL);
    float* Os0 = smem + K * MUL;                       // aliases Xs (after sync)
    float* Os1 = smem + K * MUL + REG_F;               // extra k-group partials

    const int tid  = threadIdx.x;
    const int lane = tid & 31;
    const int warp = tid >> 5;
    const int r0   = blockIdx.x * R;
    const int nrows = min(R, N - r0);
    const int ow = warp % OW;
    const int kg = warp / OW;
    const int ob = ow * TO;

    // ---- weights into smem (coalesced) ----
    #pragma unroll 1
    for (int i = tid; i < K * MUL / 4; i += NT)
        ((float4*)Ws)[i] = ((const float4*)(g_wt + WOFF))[i];

    // ---- accumulators (bias only in k-group 0) ----
    u64 acc[TC][TOH];
    #pragma unroll
    for (int p = 0; p < TOH; p++) {
        u64 bp = (kg == 0) ? pack2(__ldg(bias + ob + 2 * p), __ldg(bias + ob + 2 * p + 1))
                           : pack2(0.0f, 0.0f);
        #pragma unroll
        for (int i = 0; i < TC; i++) acc[i][p] = bp;
    }

    const int nwork_ld = nrows * CHF4;

    #pragma unroll
    for (int ph = 0; ph < KPH; ph++) {
        if (ph > 0) __syncthreads();   // previous GEMM done reading Xs

        // ---- load X chunk: float4 gmem -> duplicated u64 pairs in Xs ----
        #pragma unroll 1
        for (int i = tid; i < nwork_ld; i += NT) {
            int r = i / CHF4;
            int q = i - r * CHF4;
            float4 v = *(const float4*)(x + (size_t)(r0 + r) * ROWLEN + IN_OFF + ph * CHLEN + 4 * q);
            int j = 4 * q;
            float vv[4] = {v.x, v.y, v.z, v.w};
            #pragma unroll
            for (int e = 0; e < 4; e++) {
                int jj = j + e;
                int kl = jj / D;
                int dd = jj - kl * D;
                Xs[kl * PCp + r * D + dd] = pack2(vv[e], vv[e]);
            }
        }
        __syncthreads();

        // ---- GEMM over this phase's k range ----
        const int kbeg = kg * KLEN;
        #pragma unroll 4
        for (int kl = kbeg; kl < kbeg + KLEN; kl++) {
            u64 xp[TC];
            #pragma unroll
            for (int i = 0; i < TC; i++)
                xp[i] = Xs[kl * PCp + lane + 32 * i];
            const u64* wrow = (const u64*)(Ws + (ph * KCH + kl) * MUL + ob);
            u64 wp[TOH];
            #pragma unroll
            for (int p = 0; p < TOH; p++) wp[p] = wrow[p];
            #pragma unroll
            for (int i = 0; i < TC; i++)
                #pragma unroll
                for (int p = 0; p < TOH; p++)
                    acc[i][p] = ffma2(xp[i], wp[p], acc[i][p]);
        }
    }
    __syncthreads();   // all Xs reads done; Os0 may overwrite

    // ---- stage accumulators (conflict-free: banks = lane * odd) ----
    {
        float* Og = (kg == 0) ? Os0 : (Os1 + (kg - 1) * OS_F);
        #pragma unroll
        for (int i = 0; i < TC; i++) {
            int c = lane + 32 * i;
            #pragma unroll
            for (int p = 0; p < TOH; p++) {
                float lo, hi; unpack2(acc[i][p], lo, hi);
                Og[c * PO + ob + 2 * p]     = lo;
                Og[c * PO + ob + 2 * p + 1] = hi;
            }
        }
    }
    __syncthreads();

    // ---- epilogue: combine k-groups, activation, coalesced float4 store ----
    const int nwork_st = nrows * SEGF4;
    #pragma unroll 1
    for (int i = tid; i < nwork_st; i += NT) {
        int r = i / SEGF4;
        int q = i - r * SEGF4;
        int j = 4 * q;
        float vv[4];
        #pragma unroll
        for (int e = 0; e < 4; e++) {
            int jj = j + e;
            int o  = jj / D;
            int dd = jj - o * D;
            float v = Os0[(r * D + dd) * PO + o];
            if (KSPLIT > 1) {
                #pragma unroll
                for (int g = 1; g < KSPLIT; g++)
                    v += Os1[(g - 1) * OS_F + (r * D + dd) * PO + o];
            }
            if (ACT) v = act_fn(v);
            vv[e] = v;
        }
        float4 v; v.x = vv[0]; v.y = vv[1]; v.z = vv[2]; v.w = vv[3];
        *(float4*)(out + (size_t)(r0 + r) * ROWLEN + IN_OFF + 4 * q) = v;
    }
}

// ---- per-segment smem sizes (bytes) ----
template<int MUL, int D, int R, int KSPLIT, int KPH>
constexpr int seg_smem() {
    constexpr int CBLK = R * D;
    constexpr int XS2  = (MUL / KPH) * (CBLK + 1) * 2;
    constexpr int OS   = CBLK * (MUL + 1);
    constexpr int REG  = (XS2 > OS ? XS2 : OS);
    return (MUL * MUL + REG + (KSPLIT - 1) * OS) * 4;
}

extern "C" void kernel_launch(void* const* d_in, const int* in_sizes, int n_in,
                              void* d_out, int out_size) {
    const float* x  = (const float*)d_in[0];
    const float* w0 = (const float*)d_in[1];
    const float* w1 = (const float*)d_in[2];
    const float* w2 = (const float*)d_in[3];
    const float* w3 = (const float*)d_in[4];
    const float* b0 = (const float*)d_in[5];
    const float* b1 = (const float*)d_in[6];
    const float* b2 = (const float*)d_in[7];
    const float* b3 = (const float*)d_in[8];
    float* out = (float*)d_out;
    const int N = in_sizes[0] / ROWLEN;

    //                 MUL  D   R  NW  TO KS KPH IN_OFF  WOFF   ACT  MINB
    auto k0 = seg_kernel<128, 1, 64, 8, 16, 1, 2,    0,     0,  true, 2>;
    auto k1 = seg_kernel< 64, 3, 64, 8,  8, 1, 2,  128, 16384, false, 3>;
    auto k2 = seg_kernel< 32, 5, 32, 4,  8, 1, 1,  320, 20480, false, 5>;
    auto k3 = seg_kernel< 16, 7, 32, 4,  8, 2, 1,  480, 21504, false, 5>;

    constexpr int S0 = seg_smem<128, 1, 64, 1, 2>();  // 98816
    constexpr int S1 = seg_smem< 64, 3, 64, 1, 2>();  // 66304
    constexpr int S2 = seg_smem< 32, 5, 32, 1, 1>();  // 45312
    constexpr int S3 = seg_smem< 16, 7, 32, 2, 1>();  // 45056

    cudaFuncSetAttribute(k0, cudaFuncAttributeMaxDynamicSharedMemorySize, S0);
    cudaFuncSetAttribute(k1, cudaFuncAttributeMaxDynamicSharedMemorySize, S1);
    cudaFuncSetAttribute(k2, cudaFuncAttributeMaxDynamicSharedMemorySize, S2);
    cudaFuncSetAttribute(k3, cudaFuncAttributeMaxDynamicSharedMemorySize, S3);

    prep_kernel<<<85, 256>>>(w0, w1, w2, w3);

    const int g64 = (N + 63) / 64;   // 1563
    const int g32 = (N + 31) / 32;   // 3125
    k0<<<g64, 256, S0>>>(x, b0, out, N);
    k1<<<g64, 256, S1>>>(x, b1, out, N);
    k2<<<g32, 128, S2>>>(x, b2, out, N);
    k3<<<g32, 128, S3>>>(x, b3, out, N);
}